// round 9
// baseline (speedup 1.0000x reference)
#include <cuda_runtime.h>
#include <cuda_bf16.h>
#include <cstdint>

// Round 9: fused producer-consumer. 128 CTAs x 288 threads.
//   threads [0,256): round-7 scan (REG_K=72 reg rows + SMK=56 smem rows of R,
//                    FFMA2 mainloop, shuffle epilogue, 1 barrier/step)
//   threads [256,288): producer warp - computes pre = x@W^T for THIS CTA's two
//                    batch rows via bf16 3-term-split HMMA, 16 steps ahead,
//                    stores to the 1GB g_pre scratch (consumed by same CTA).
// prep_w kernel packs W into bf16 hi/lo fragment-ready buffers (L2-resident).

#define BB 256
#define SS 2048
#define II 64
#define HH 128
#define GG 512
#define NCTA 128
#define NTHR 288

#define REG_K 72
#define SMK   56
#define PTS  (SMK * 2 + 4)          // 116 floats; (116 mod 32)=20 -> conflict-free
#define SW_FLOATS (256 * PTS)
#define HB_FLOATS (2 * 2 * HH)
#define SCAN_SMEM_BYTES ((SW_FLOATS + HB_FLOATS) * 4)

typedef unsigned long long u64;

__device__ float g_pre[(long long)BB * SS * GG];        // 1 GB scratch
__device__ __align__(16) unsigned g_wh[GG * II / 2];    // W hi bf16 pairs [g*32+k/2]
__device__ __align__(16) unsigned g_wl[GG * II / 2];    // W lo residual

__device__ __forceinline__ u64 ffma2(u64 a, u64 b, u64 c) {
    u64 d;
    asm("fma.rn.f32x2 %0, %1, %2, %3;" : "=l"(d) : "l"(a), "l"(b), "l"(c));
    return d;
}
__device__ __forceinline__ u64 packf2(float lo, float hi) {
    u64 r;
    asm("mov.b64 %0, {%1, %2};" : "=l"(r) : "f"(lo), "f"(hi));
    return r;
}
__device__ __forceinline__ float2 unpackf2(u64 v) {
    float2 r;
    asm("mov.b64 {%0, %1}, %2;" : "=f"(r.x), "=f"(r.y) : "l"(v));
    return r;
}
__device__ __forceinline__ float fast_tanh(float x) {
    float xc = fminf(fmaxf(x, -12.0f), 12.0f);
    float e  = __expf(2.0f * xc);
    return __fdividef(e - 1.0f, e + 1.0f);
}
__device__ __forceinline__ unsigned pack_bf16_hi(float a, float b) {
    __nv_bfloat16 ah = __float2bfloat16(a), bh = __float2bfloat16(b);
    return (unsigned)__bfloat16_as_ushort(ah) | ((unsigned)__bfloat16_as_ushort(bh) << 16);
}
__device__ __forceinline__ unsigned pack_bf16_lo(float a, float b) {
    __nv_bfloat16 ah = __float2bfloat16(a), bh = __float2bfloat16(b);
    __nv_bfloat16 al = __float2bfloat16(a - __bfloat162float(ah));
    __nv_bfloat16 bl = __float2bfloat16(b - __bfloat162float(bh));
    return (unsigned)__bfloat16_as_ushort(al) | ((unsigned)__bfloat16_as_ushort(bl) << 16);
}
__device__ __forceinline__ void mma16816(float* c, const unsigned* a,
                                         unsigned b0, unsigned b1) {
    asm volatile(
        "mma.sync.aligned.m16n8k16.row.col.f32.bf16.bf16.f32 "
        "{%0,%1,%2,%3}, {%4,%5,%6,%7}, {%8,%9}, {%0,%1,%2,%3};"
        : "+f"(c[0]), "+f"(c[1]), "+f"(c[2]), "+f"(c[3])
        : "r"(a[0]), "r"(a[1]), "r"(a[2]), "r"(a[3]), "r"(b0), "r"(b1));
}

__global__ void prep_w_kernel(const float* __restrict__ Wm) {
    int i = blockIdx.x * 256 + threadIdx.x;
    float a = Wm[2 * i], b = Wm[2 * i + 1];
    g_wh[i] = pack_bf16_hi(a, b);
    g_wl[i] = pack_bf16_lo(a, b);
}

// ---------------------------------------------------------------------------
// Producer helpers: one warp computes pre tile (2 rows x 8 steps x 512 cols).
// A tile: m16 = [row0 sofs0..7 ; row1 sofs0..7], k=64. B = W (fragment-packed
// in g_wh/g_wl). 3-term split: AhBh + AlBh + AhBl, fp32 accum.
// ---------------------------------------------------------------------------
struct AFrag { unsigned h[4][4]; unsigned l[4][4]; };   // [ks][j]

__device__ __forceinline__ void prod_load_A(AFrag& A, const float* __restrict__ xg,
                                            int b0, int sbase, int gid, int tig) {
    const float* x0 = xg + ((long long)b0 * SS + sbase + gid) * II;
    const float* x1 = xg + ((long long)(b0 + 1) * SS + sbase + gid) * II;
#pragma unroll
    for (int ks = 0; ks < 4; ks++) {
        int k = 16 * ks + 2 * tig;
        float2 v0 = __ldg((const float2*)(x0 + k));        // a0: row0, k
        float2 v1 = __ldg((const float2*)(x1 + k));        // a1: row1, k
        float2 v2 = __ldg((const float2*)(x0 + k + 8));    // a2: row0, k+8
        float2 v3 = __ldg((const float2*)(x1 + k + 8));    // a3: row1, k+8
        A.h[ks][0] = pack_bf16_hi(v0.x, v0.y);  A.l[ks][0] = pack_bf16_lo(v0.x, v0.y);
        A.h[ks][1] = pack_bf16_hi(v1.x, v1.y);  A.l[ks][1] = pack_bf16_lo(v1.x, v1.y);
        A.h[ks][2] = pack_bf16_hi(v2.x, v2.y);  A.l[ks][2] = pack_bf16_lo(v2.x, v2.y);
        A.h[ks][3] = pack_bf16_hi(v3.x, v3.y);  A.l[ks][3] = pack_bf16_lo(v3.x, v3.y);
    }
}

// process n-tiles [nt0, nt0+cnt) of the current tile (64 n-tiles total)
__device__ __forceinline__ void prod_ntiles(const AFrag& A, float* pre,
                                            int b0, int sbase, int gid, int tig,
                                            int nt0, int cnt) {
    long long s = sbase + gid;
    float* o0 = pre + ((long long)b0 * SS + s) * GG + tig * 2;
    float* o1 = pre + ((long long)(b0 + 1) * SS + s) * GG + tig * 2;
#pragma unroll 4
    for (int q = 0; q < cnt; q++) {
        int nt = nt0 + q;
        int n  = nt * 8 + gid;
        const unsigned* whp = g_wh + n * 32;
        const unsigned* wlp = g_wl + n * 32;
        float acc[4] = {0.f, 0.f, 0.f, 0.f};
#pragma unroll
        for (int ks = 0; ks < 4; ks++) {
            unsigned bh0 = __ldg(whp + ks * 8 + tig);
            unsigned bh1 = __ldg(whp + ks * 8 + tig + 4);
            unsigned bl0 = __ldg(wlp + ks * 8 + tig);
            unsigned bl1 = __ldg(wlp + ks * 8 + tig + 4);
            mma16816(acc, A.h[ks], bh0, bh1);
            mma16816(acc, A.l[ks], bh0, bh1);
            mma16816(acc, A.h[ks], bl0, bl1);
        }
        *(float2*)(o0 + nt * 8) = make_float2(acc[0], acc[1]);   // row0
        *(float2*)(o1 + nt * 8) = make_float2(acc[2], acc[3]);   // row1
    }
}

// ---------------------------------------------------------------------------
__global__ void __launch_bounds__(NTHR, 1)
slstm_fused_kernel(const float* __restrict__ xg, const float* __restrict__ Rm,
                   const float* __restrict__ bias, float* pre,
                   float* __restrict__ out)
{
    extern __shared__ float smem[];
    float* sW = smem;                    // [256][PTS]
    float* hb = smem + SW_FLOATS;        // [2][2][HH]

    const int tid = threadIdx.x;
    const int b0  = blockIdx.x * 2;
    const bool is_scan = (tid < 256);

    // ---------------- producer state ----------------
    const int ptid = tid - 256;
    const int gid  = ptid >> 2;
    const int tig  = ptid & 3;
    AFrag A;

    // ---------------- scan setup ----------------
    const int w  = tid >> 5;             // 0..7 for scan threads
    const int l  = tid & 31;
    const int c0 = 16 * l + 2 * (w & 7);
    const int c1 = c0 + 1;

    u64 wp0[REG_K / 2], wp1[REG_K / 2];
    float bg0 = 0.f, bg1 = 0.f;

    if (is_scan) {
#pragma unroll
        for (int j = 0; j < REG_K / 2; j++) {
            wp0[j] = packf2(Rm[(2 * j) * GG + c0], Rm[(2 * j + 1) * GG + c0]);
            wp1[j] = packf2(Rm[(2 * j) * GG + c1], Rm[(2 * j + 1) * GG + c1]);
        }
        float* slab = sW + tid * PTS;
#pragma unroll
        for (int kc = 0; kc < SMK; kc += 4) {
            int k = REG_K + kc;
            slab[kc * 2 + 0] = Rm[(k + 0) * GG + c0];
            slab[kc * 2 + 1] = Rm[(k + 1) * GG + c0];
            slab[kc * 2 + 2] = Rm[(k + 0) * GG + c1];
            slab[kc * 2 + 3] = Rm[(k + 1) * GG + c1];
            slab[kc * 2 + 4] = Rm[(k + 2) * GG + c0];
            slab[kc * 2 + 5] = Rm[(k + 3) * GG + c0];
            slab[kc * 2 + 6] = Rm[(k + 2) * GG + c1];
            slab[kc * 2 + 7] = Rm[(k + 3) * GG + c1];
        }
        bg0 = bias[c0];
        bg1 = bias[c1];
        hb[tid] = 0.0f;
        hb[tid + 256] = 0.0f;
    } else {
        // prologue: produce tiles for steps [0,8) and [8,16)
        prod_load_A(A, xg, b0, 0, gid, tig);
        prod_ntiles(A, pre, b0, 0, gid, tig, 0, 32);
        prod_ntiles(A, pre, b0, 0, gid, tig, 32, 32);
        prod_load_A(A, xg, b0, 8, gid, tig);
        prod_ntiles(A, pre, b0, 8, gid, tig, 0, 32);
        prod_ntiles(A, pre, b0, 8, gid, tig, 32, 32);
    }
    __syncthreads();

    const float* pr0 = pre + (long long)(b0)     * SS * GG;
    const float* pr1 = pre + (long long)(b0 + 1) * SS * GG;

    float2 p0 = make_float2(0.f, 0.f), p1 = make_float2(0.f, 0.f);
    if (is_scan) {
        p0 = *(const float2*)(pr0 + c0);
        p1 = *(const float2*)(pr1 + c0);
    }

    const int my_row = (l >> 4) & 1;
    const int my_hid = 16 * (l & 7) + 2 * (w & 7) + ((l >> 3) & 1);
    float c_ = 0.0f, n_ = 0.0f, m_ = 0.0f;

    const bool lo16 = (l < 16);
    const bool b3   = ((l >> 3) & 1) != 0;
    const float* sWg = sW + tid * PTS;

#pragma unroll 1
    for (int step = 0; step < SS; step++) {
        if (is_scan) {
            const float* h0 = hb + (step & 1) * 256;
            const float* h1 = h0 + HH;
            float* hn = hb + ((step + 1) & 1) * 256;

            float2 q0 = make_float2(0.f, 0.f), q1 = make_float2(0.f, 0.f);
            if (step + 1 < SS) {
                long long off = (long long)(step + 1) * GG;
                q0 = *(const float2*)(pr0 + off + c0);
                q1 = *(const float2*)(pr1 + off + c0);
            }

            u64 a00 = 0, a10 = 0, a01 = 0, a11 = 0;

#pragma unroll
            for (int k = 0; k < REG_K; k += 4) {
                ulonglong2 hp0 = *(const ulonglong2*)(h0 + k);
                ulonglong2 hp1 = *(const ulonglong2*)(h1 + k);
                int j = k / 2;
                a00 = ffma2(hp0.x, wp0[j],     a00);
                a10 = ffma2(hp0.x, wp1[j],     a10);
                a01 = ffma2(hp1.x, wp0[j],     a01);
                a11 = ffma2(hp1.x, wp1[j],     a11);
                a00 = ffma2(hp0.y, wp0[j + 1], a00);
                a10 = ffma2(hp0.y, wp1[j + 1], a10);
                a01 = ffma2(hp1.y, wp0[j + 1], a01);
                a11 = ffma2(hp1.y, wp1[j + 1], a11);
            }
#pragma unroll
            for (int k = 0; k < SMK; k += 4) {
                ulonglong2 wv0 = *(const ulonglong2*)(sWg + k * 2);
                ulonglong2 wv1 = *(const ulonglong2*)(sWg + k * 2 + 4);
                ulonglong2 hp0 = *(const ulonglong2*)(h0 + REG_K + k);
                ulonglong2 hp1 = *(const ulonglong2*)(h1 + REG_K + k);
                a00 = ffma2(hp0.x, wv0.x, a00);
                a10 = ffma2(hp0.x, wv0.y, a10);
                a01 = ffma2(hp1.x, wv0.x, a01);
                a11 = ffma2(hp1.x, wv0.y, a11);
                a00 = ffma2(hp0.y, wv1.x, a00);
                a10 = ffma2(hp0.y, wv1.y, a10);
                a01 = ffma2(hp1.y, wv1.x, a01);
                a11 = ffma2(hp1.y, wv1.y, a11);
            }

            float2 t0 = unpackf2(a00), t1 = unpackf2(a10);
            float2 t2 = unpackf2(a01), t3 = unpackf2(a11);
            float aa = t0.x + t0.y + p0.x + bg0;   // g(r0, c0)
            float bb = t1.x + t1.y + p0.y + bg1;   // g(r0, c1)
            float cc = t2.x + t2.y + p1.x + bg0;   // g(r1, c0)
            float dd = t3.x + t3.y + p1.y + bg1;   // g(r1, c1)

            // warp-local gate transpose (4 shuffles)
            float u1 = lo16 ? cc : aa;
            float u2 = lo16 ? dd : bb;
            float r1v = __shfl_xor_sync(0xFFFFFFFFu, u1, 16);
            float r2v = __shfl_xor_sync(0xFFFFFFFFu, u2, 16);
            float Ag = lo16 ? aa : r1v;
            float Bg = lo16 ? bb : r2v;
            float Cg = lo16 ? r1v : cc;
            float Dg = lo16 ? r2v : dd;
            float s1in = b3 ? Ag : Bg;
            float s2in = b3 ? Cg : Dg;
            float e1 = __shfl_xor_sync(0xFFFFFFFFu, s1in, 8);
            float e2 = __shfl_xor_sync(0xFFFFFFFFu, s2in, 8);
            float iv = b3 ? e1 : Ag;
            float fv = b3 ? Bg : e1;
            float ov = b3 ? e2 : Cg;
            float zv = b3 ? Dg : e2;

            float tz = fast_tanh(zv);
            float so = __fdividef(1.0f, 1.0f + __expf(-ov));
            float lf = fminf(fv, 0.0f) - __logf(1.0f + __expf(-fabsf(fv)));
            float mn = fmaxf(lf + m_, iv);
            float ip = __expf(iv - mn);
            float fp = __expf(lf + m_ - mn);
            c_ = fp * c_ + ip * tz;
            n_ = fp * n_ + ip;
            m_ = mn;
            float hv = so * fast_tanh(__fdividef(c_, n_));

            hn[my_row * HH + my_hid] = hv;
            out[((long long)(b0 + my_row) * SS + step) * HH + my_hid] = hv;

            p0 = q0; p1 = q1;
        } else {
            // producer: during steps [8j, 8j+8) build tile sbase = 8j+16
            int ph    = step & 7;
            int sbase = (step & ~7) + 16;
            if (sbase < SS) {
                if (ph == 0)
                    prod_load_A(A, xg, b0, sbase, gid, tig);
                prod_ntiles(A, pre, b0, sbase, gid, tig, ph * 8, 8);
            }
        }
        __syncthreads();
    }
}

extern "C" void kernel_launch(void* const* d_in, const int* in_sizes, int n_in,
                              void* d_out, int out_size)
{
    const float* xg = (const float*)d_in[0];
    const float* Wm = (const float*)d_in[1];
    const float* Rm = (const float*)d_in[2];
    const float* bv = (const float*)d_in[3];
    if (n_in >= 3 && in_sizes[1] == HH * GG && in_sizes[2] == GG * II) {
        const float* t = Wm; Wm = Rm; Rm = t;
    }
    float* out = (float*)d_out;

    float* pre = nullptr;
    cudaGetSymbolAddress((void**)&pre, g_pre);

    cudaFuncSetAttribute(slstm_fused_kernel,
                         cudaFuncAttributeMaxDynamicSharedMemorySize, SCAN_SMEM_BYTES);

    prep_w_kernel<<<GG * II / 2 / 256, 256>>>(Wm);
    slstm_fused_kernel<<<NCTA, NTHR, SCAN_SMEM_BYTES>>>(xg, Rm, bv, pre, out);
}

// round 10
// speedup vs baseline: 2.1544x; 2.1544x over previous
#include <cuda_runtime.h>
#include <cuda_bf16.h>
#include <cstdint>

// Round 10: fused scan + FREE-RUNNING producer warp (decoupled via smem flag).
// 128 CTAs x 288 threads:
//   threads [0,256): round-7 scan (REG_K=80 reg rows + SMK=48 smem rows of R,
//                    FFMA2 mainloop, shuffle epilogue, named barrier 1)
//   threads [256,288): producer warp free-runs pre = x@W^T for this CTA's two
//                    batch rows (bf16 3-term HMMA), s-ascending, publishing a
//                    progress flag; never touches the scan barrier.

#define BB 256
#define SS 2048
#define II 64
#define HH 128
#define GG 512
#define NCTA 128
#define NTHR 288

#define REG_K 80
#define SMK   48
#define PTS  (SMK * 2 + 4)          // 100 floats; 100 mod 32 == 4 (proven pattern)
#define SW_FLOATS (256 * PTS)
#define HB_FLOATS (2 * 2 * HH)
#define SCAN_SMEM_BYTES ((SW_FLOATS + HB_FLOATS + 8) * 4)

typedef unsigned long long u64;

__device__ float g_pre[(long long)BB * SS * GG];          // 1 GB scratch
__device__ __align__(16) unsigned g_whf[GG * 4 * 8];      // W hi, fragment-major
__device__ __align__(16) unsigned g_wlf[GG * 4 * 8];      // W lo residual

__device__ __forceinline__ u64 ffma2(u64 a, u64 b, u64 c) {
    u64 d;
    asm("fma.rn.f32x2 %0, %1, %2, %3;" : "=l"(d) : "l"(a), "l"(b), "l"(c));
    return d;
}
__device__ __forceinline__ u64 packf2(float lo, float hi) {
    u64 r;
    asm("mov.b64 %0, {%1, %2};" : "=l"(r) : "f"(lo), "f"(hi));
    return r;
}
__device__ __forceinline__ float2 unpackf2(u64 v) {
    float2 r;
    asm("mov.b64 {%0, %1}, %2;" : "=f"(r.x), "=f"(r.y) : "l"(v));
    return r;
}
__device__ __forceinline__ float fast_tanh(float x) {
    float xc = fminf(fmaxf(x, -12.0f), 12.0f);
    float e  = __expf(2.0f * xc);
    return __fdividef(e - 1.0f, e + 1.0f);
}
__device__ __forceinline__ unsigned pack_bf16_hi(float a, float b) {
    __nv_bfloat16 ah = __float2bfloat16(a), bh = __float2bfloat16(b);
    return (unsigned)__bfloat16_as_ushort(ah) | ((unsigned)__bfloat16_as_ushort(bh) << 16);
}
__device__ __forceinline__ unsigned pack_bf16_lo(float a, float b) {
    __nv_bfloat16 ah = __float2bfloat16(a), bh = __float2bfloat16(b);
    __nv_bfloat16 al = __float2bfloat16(a - __bfloat162float(ah));
    __nv_bfloat16 bl = __float2bfloat16(b - __bfloat162float(bh));
    return (unsigned)__bfloat16_as_ushort(al) | ((unsigned)__bfloat16_as_ushort(bl) << 16);
}
__device__ __forceinline__ void mma16816(float* c, const unsigned* a,
                                         unsigned b0, unsigned b1) {
    asm volatile(
        "mma.sync.aligned.m16n8k16.row.col.f32.bf16.bf16.f32 "
        "{%0,%1,%2,%3}, {%4,%5,%6,%7}, {%8,%9}, {%0,%1,%2,%3};"
        : "+f"(c[0]), "+f"(c[1]), "+f"(c[2]), "+f"(c[3])
        : "r"(a[0]), "r"(a[1]), "r"(a[2]), "r"(a[3]), "r"(b0), "r"(b1));
}

// ---------------------------------------------------------------------------
// prep: W fp32 -> bf16 hi/lo, FRAGMENT-MAJOR: g_whf[(n*4+tig)*8 + ks*2 + j]
//   = pack(W[n][2u], W[n][2u+1]),  u = ks*8 + tig + 4*j
// ---------------------------------------------------------------------------
__global__ void prep_w_kernel(const float* __restrict__ Wm) {
    int i = blockIdx.x * 256 + threadIdx.x;   // 8192 = 512n * 4tig * 4ks
    int n = i >> 4, tig = (i >> 2) & 3, ks = i & 3;
#pragma unroll
    for (int j = 0; j < 2; j++) {
        int u = ks * 8 + tig + 4 * j;
        float a = Wm[n * II + 2 * u], b = Wm[n * II + 2 * u + 1];
        int o = (n * 4 + tig) * 8 + ks * 2 + j;
        g_whf[o] = pack_bf16_hi(a, b);
        g_wlf[o] = pack_bf16_lo(a, b);
    }
}

// ---------------------------------------------------------------------------
// Producer: one warp, tile = 2 rows x 8 steps x 512 cols, 3-term bf16 HMMA.
// m16 rows: gid -> (row0, s=sbase+gid), gid+8 -> (row1, s=sbase+gid).
// ---------------------------------------------------------------------------
struct AFrag { unsigned h[4][4]; unsigned l[4][4]; };

__device__ __forceinline__ void prod_load_A(AFrag& A, const float* __restrict__ xg,
                                            int b0, int sbase, int gid, int tig) {
    const float* x0 = xg + ((long long)b0 * SS + sbase + gid) * II;
    const float* x1 = xg + ((long long)(b0 + 1) * SS + sbase + gid) * II;
#pragma unroll
    for (int ks = 0; ks < 4; ks++) {
        int k = 16 * ks + 2 * tig;
        float2 v0 = __ldg((const float2*)(x0 + k));
        float2 v1 = __ldg((const float2*)(x1 + k));
        float2 v2 = __ldg((const float2*)(x0 + k + 8));
        float2 v3 = __ldg((const float2*)(x1 + k + 8));
        A.h[ks][0] = pack_bf16_hi(v0.x, v0.y);  A.l[ks][0] = pack_bf16_lo(v0.x, v0.y);
        A.h[ks][1] = pack_bf16_hi(v1.x, v1.y);  A.l[ks][1] = pack_bf16_lo(v1.x, v1.y);
        A.h[ks][2] = pack_bf16_hi(v2.x, v2.y);  A.l[ks][2] = pack_bf16_lo(v2.x, v2.y);
        A.h[ks][3] = pack_bf16_hi(v3.x, v3.y);  A.l[ks][3] = pack_bf16_lo(v3.x, v3.y);
    }
}

__device__ __forceinline__ void prod_tile(const AFrag& A, float* pre,
                                          int b0, int sbase, int gid, int tig) {
    long long s = sbase + gid;
    float* o0 = pre + ((long long)b0 * SS + s) * GG + tig * 2;
    float* o1 = pre + ((long long)(b0 + 1) * SS + s) * GG + tig * 2;
#pragma unroll 4
    for (int nt = 0; nt < 64; nt++) {
        int n = nt * 8 + gid;
        const uint4* whp = (const uint4*)(g_whf + (n * 4 + tig) * 8);
        const uint4* wlp = (const uint4*)(g_wlf + (n * 4 + tig) * 8);
        uint4 H0 = __ldg(whp),     H1 = __ldg(whp + 1);
        uint4 L0 = __ldg(wlp),     L1 = __ldg(wlp + 1);
        unsigned bh[8] = {H0.x, H0.y, H0.z, H0.w, H1.x, H1.y, H1.z, H1.w};
        unsigned bl[8] = {L0.x, L0.y, L0.z, L0.w, L1.x, L1.y, L1.z, L1.w};
        float acc[4] = {0.f, 0.f, 0.f, 0.f};
#pragma unroll
        for (int ks = 0; ks < 4; ks++) {
            mma16816(acc, A.h[ks], bh[ks * 2], bh[ks * 2 + 1]);
            mma16816(acc, A.l[ks], bh[ks * 2], bh[ks * 2 + 1]);
            mma16816(acc, A.h[ks], bl[ks * 2], bl[ks * 2 + 1]);
        }
        *(float2*)(o0 + nt * 8) = make_float2(acc[0], acc[1]);
        *(float2*)(o1 + nt * 8) = make_float2(acc[2], acc[3]);
    }
}

// ---------------------------------------------------------------------------
__global__ void __launch_bounds__(NTHR, 1)
slstm_fused_kernel(const float* __restrict__ xg, const float* __restrict__ Rm,
                   const float* __restrict__ bias, float* pre,
                   float* __restrict__ out)
{
    extern __shared__ float smem[];
    float* sW = smem;                                 // [256][PTS]
    float* hb = smem + SW_FLOATS;                     // [2][2][HH]
    volatile int* flagp = (volatile int*)(smem + SW_FLOATS + HB_FLOATS);

    const int tid = threadIdx.x;
    const int b0  = blockIdx.x * 2;
    const bool is_scan = (tid < 256);

    const int w  = tid >> 5;
    const int l  = tid & 31;
    const int c0 = 16 * l + 2 * (w & 7);
    const int c1 = c0 + 1;

    u64 wp0[REG_K / 2], wp1[REG_K / 2];
    float bg0 = 0.f, bg1 = 0.f;

    if (tid == 0) *flagp = 0;

    if (is_scan) {
#pragma unroll
        for (int j = 0; j < REG_K / 2; j++) {
            wp0[j] = packf2(Rm[(2 * j) * GG + c0], Rm[(2 * j + 1) * GG + c0]);
            wp1[j] = packf2(Rm[(2 * j) * GG + c1], Rm[(2 * j + 1) * GG + c1]);
        }
        float* slab = sW + tid * PTS;
#pragma unroll
        for (int kc = 0; kc < SMK; kc += 4) {
            int k = REG_K + kc;
            slab[kc * 2 + 0] = Rm[(k + 0) * GG + c0];
            slab[kc * 2 + 1] = Rm[(k + 1) * GG + c0];
            slab[kc * 2 + 2] = Rm[(k + 0) * GG + c1];
            slab[kc * 2 + 3] = Rm[(k + 1) * GG + c1];
            slab[kc * 2 + 4] = Rm[(k + 2) * GG + c0];
            slab[kc * 2 + 5] = Rm[(k + 3) * GG + c0];
            slab[kc * 2 + 6] = Rm[(k + 2) * GG + c1];
            slab[kc * 2 + 7] = Rm[(k + 3) * GG + c1];
        }
        bg0 = bias[c0];
        bg1 = bias[c1];
        hb[tid] = 0.0f;
        hb[tid + 256] = 0.0f;
    }
    __syncthreads();     // the ONLY full-block barrier

    if (!is_scan) {
        // ---------------- free-running producer ----------------
        const int ptid = tid - 256;
        const int gid  = ptid >> 2;
        const int tig  = ptid & 3;
        AFrag A;
#pragma unroll 1
        for (int tile = 0; tile < SS / 8; tile++) {
            prod_load_A(A, xg, b0, tile * 8, gid, tig);
            prod_tile(A, pre, b0, tile * 8, gid, tig);
            __threadfence_block();                    // order STG before flag
            if ((tid & 31) == 0) *flagp = (tile + 1) * 8;
        }
        return;                                       // producer warp exits
    }

    // ---------------- scan ----------------
    const float* pr0 = pre + (long long)(b0)     * SS * GG;
    const float* pr1 = pre + (long long)(b0 + 1) * SS * GG;

    int seen = 0;
#define WAITS(need) do { int _n = (need); if (seen < _n) {                       \
        while ((seen = *flagp) < _n) {}                                          \
        __threadfence_block(); } } while (0)

    WAITS(2);
    float2 p0 = *(const float2*)(pr0 + c0);
    float2 p1 = *(const float2*)(pr1 + c0);

    const int my_row = (l >> 4) & 1;
    const int my_hid = 16 * (l & 7) + 2 * (w & 7) + ((l >> 3) & 1);
    float c_ = 0.0f, n_ = 0.0f, m_ = 0.0f;

    const bool lo16 = (l < 16);
    const bool b3   = ((l >> 3) & 1) != 0;
    const float* sWg = sW + tid * PTS;

#pragma unroll 1
    for (int step = 0; step < SS; step++) {
        const float* h0 = hb + (step & 1) * 256;
        const float* h1 = h0 + HH;
        float* hn = hb + ((step + 1) & 1) * 256;

        float2 q0 = make_float2(0.f, 0.f), q1 = make_float2(0.f, 0.f);
        if (step + 1 < SS) {
            WAITS(step + 2);
            long long off = (long long)(step + 1) * GG;
            q0 = *(const float2*)(pr0 + off + c0);
            q1 = *(const float2*)(pr1 + off + c0);
        }

        u64 a00 = 0, a10 = 0, a01 = 0, a11 = 0;

#pragma unroll
        for (int k = 0; k < REG_K; k += 4) {
            ulonglong2 hp0 = *(const ulonglong2*)(h0 + k);
            ulonglong2 hp1 = *(const ulonglong2*)(h1 + k);
            int j = k / 2;
            a00 = ffma2(hp0.x, wp0[j],     a00);
            a10 = ffma2(hp0.x, wp1[j],     a10);
            a01 = ffma2(hp1.x, wp0[j],     a01);
            a11 = ffma2(hp1.x, wp1[j],     a11);
            a00 = ffma2(hp0.y, wp0[j + 1], a00);
            a10 = ffma2(hp0.y, wp1[j + 1], a10);
            a01 = ffma2(hp1.y, wp0[j + 1], a01);
            a11 = ffma2(hp1.y, wp1[j + 1], a11);
        }
#pragma unroll
        for (int k = 0; k < SMK; k += 4) {
            ulonglong2 wv0 = *(const ulonglong2*)(sWg + k * 2);
            ulonglong2 wv1 = *(const ulonglong2*)(sWg + k * 2 + 4);
            ulonglong2 hp0 = *(const ulonglong2*)(h0 + REG_K + k);
            ulonglong2 hp1 = *(const ulonglong2*)(h1 + REG_K + k);
            a00 = ffma2(hp0.x, wv0.x, a00);
            a10 = ffma2(hp0.x, wv0.y, a10);
            a01 = ffma2(hp1.x, wv0.x, a01);
            a11 = ffma2(hp1.x, wv0.y, a11);
            a00 = ffma2(hp0.y, wv1.x, a00);
            a10 = ffma2(hp0.y, wv1.y, a10);
            a01 = ffma2(hp1.y, wv1.x, a01);
            a11 = ffma2(hp1.y, wv1.y, a11);
        }

        float2 t0 = unpackf2(a00), t1 = unpackf2(a10);
        float2 t2 = unpackf2(a01), t3 = unpackf2(a11);
        float aa = t0.x + t0.y + p0.x + bg0;
        float bb = t1.x + t1.y + p0.y + bg1;
        float cc = t2.x + t2.y + p1.x + bg0;
        float dd = t3.x + t3.y + p1.y + bg1;

        // warp-local gate transpose (4 shuffles)
        float u1 = lo16 ? cc : aa;
        float u2 = lo16 ? dd : bb;
        float r1v = __shfl_xor_sync(0xFFFFFFFFu, u1, 16);
        float r2v = __shfl_xor_sync(0xFFFFFFFFu, u2, 16);
        float Ag = lo16 ? aa : r1v;
        float Bg = lo16 ? bb : r2v;
        float Cg = lo16 ? r1v : cc;
        float Dg = lo16 ? r2v : dd;
        float s1in = b3 ? Ag : Bg;
        float s2in = b3 ? Cg : Dg;
        float e1 = __shfl_xor_sync(0xFFFFFFFFu, s1in, 8);
        float e2 = __shfl_xor_sync(0xFFFFFFFFu, s2in, 8);
        float iv = b3 ? e1 : Ag;
        float fv = b3 ? Bg : e1;
        float ov = b3 ? e2 : Cg;
        float zv = b3 ? Dg : e2;

        float tz = fast_tanh(zv);
        float so = __fdividef(1.0f, 1.0f + __expf(-ov));
        float lf = fminf(fv, 0.0f) - __logf(1.0f + __expf(-fabsf(fv)));
        float mn = fmaxf(lf + m_, iv);
        float ip = __expf(iv - mn);
        float fp = __expf(lf + m_ - mn);
        c_ = fp * c_ + ip * tz;
        n_ = fp * n_ + ip;
        m_ = mn;
        float hv = so * fast_tanh(__fdividef(c_, n_));

        hn[my_row * HH + my_hid] = hv;
        out[((long long)(b0 + my_row) * SS + step) * HH + my_hid] = hv;

        p0 = q0; p1 = q1;
        asm volatile("bar.sync 1, 256;" ::: "memory");   // scan warps only
    }
}

extern "C" void kernel_launch(void* const* d_in, const int* in_sizes, int n_in,
                              void* d_out, int out_size)
{
    const float* xg = (const float*)d_in[0];
    const float* Wm = (const float*)d_in[1];
    const float* Rm = (const float*)d_in[2];
    const float* bv = (const float*)d_in[3];
    if (n_in >= 3 && in_sizes[1] == HH * GG && in_sizes[2] == GG * II) {
        const float* t = Wm; Wm = Rm; Rm = t;
    }
    float* out = (float*)d_out;

    float* pre = nullptr;
    cudaGetSymbolAddress((void**)&pre, g_pre);

    cudaFuncSetAttribute(slstm_fused_kernel,
                         cudaFuncAttributeMaxDynamicSharedMemorySize, SCAN_SMEM_BYTES);

    prep_w_kernel<<<32, 256>>>(Wm);
    slstm_fused_kernel<<<NCTA, NTHR, SCAN_SMEM_BYTES>>>(xg, Rm, bv, pre, out);
}